// round 1
// baseline (speedup 1.0000x reference)
#include <cuda_runtime.h>
#include <math.h>

#define N_NODES 4096
#define H 256
#define E_EDGES 131072

// ---------------- scratch (device globals: no allocs allowed) ----------------
__device__ float g_h[N_NODES*H];
__device__ float g_agg[N_NODES*H];
__device__ float g_tmp[N_NODES*H];
__device__ float g_ca[N_NODES*H];
__device__ float g_cb[N_NODES*H];
__device__ float g_fused[N_NODES*2*H];
__device__ float g_qkv[N_NODES*6*H];
__device__ float g_attn[N_NODES*2*H];
__device__ float g_o[N_NODES*2*H];
__device__ float g_o2[N_NODES*2*H];
__device__ float g_convw[9*H*H];
__device__ int   g_cnt[N_NODES];
__device__ int   g_fillp[N_NODES];
__device__ int   g_off[N_NODES+1];
__device__ int   g_csrs[E_EDGES];
__device__ float g_degf[N_NODES];

// ---------------- CSR build ----------------
__global__ void k_zero() {
    int i = blockIdx.x*256 + threadIdx.x;
    if (i < N_NODES) { g_cnt[i] = 0; g_fillp[i] = 0; }
}

__global__ void k_count(const int* __restrict__ dst) {
    int e = blockIdx.x*256 + threadIdx.x;
    if (e < E_EDGES) atomicAdd(&g_cnt[dst[e]], 1);
}

__global__ void k_scan() {
    __shared__ int ps[1024];
    int t = threadIdx.x;
    int c[4]; int s = 0;
    #pragma unroll
    for (int l = 0; l < 4; l++) { c[l] = g_cnt[t*4+l]; s += c[l]; }
    ps[t] = s;
    __syncthreads();
    for (int d = 1; d < 1024; d <<= 1) {
        int v = (t >= d) ? ps[t-d] : 0;
        __syncthreads();
        ps[t] += v;
        __syncthreads();
    }
    int base = ps[t] - s;   // exclusive prefix of this thread's chunk
    #pragma unroll
    for (int l = 0; l < 4; l++) {
        g_off[t*4+l] = base;
        base += c[l];
        g_degf[t*4+l] = (float)max(c[l], 1);
    }
    if (t == 1023) g_off[N_NODES] = ps[1023];
}

__global__ void k_fill(const int* __restrict__ src, const int* __restrict__ dst) {
    int e = blockIdx.x*256 + threadIdx.x;
    if (e < E_EDGES) {
        int d = dst[e];
        int p = atomicAdd(&g_fillp[d], 1);
        g_csrs[g_off[d] + p] = src[e];
    }
}

// ---------------- misc ----------------
__global__ void k_copy(const float* __restrict__ in, float* __restrict__ out) {
    int i = blockIdx.x*256 + threadIdx.x;
    out[i] = in[i];
}

// conv_w [3][O=256][I=256][K=3] -> wt [(j*3+k)][O][I]  (row-major B for sgemm)
__global__ void k_wtrans(const float* __restrict__ w, float* __restrict__ wt) {
    int idx = blockIdx.x*256 + threadIdx.x;
    if (idx < 9*H*H) {
        int k = idx % 3;
        int r = idx / 3;
        int i = r % H;
        int r2 = r / H;
        int o = r2 % H;
        int j = r2 / H;
        wt[((j*3+k)*H + o)*H + i] = w[idx];
    }
}

__global__ void k_concat(const float* __restrict__ a, const float* __restrict__ b,
                         float* __restrict__ o) {
    int idx = blockIdx.x*256 + threadIdx.x;   // 4096*512
    int n = idx >> 9, c = idx & 511;
    o[idx] = (c < H) ? a[n*H + c] : b[n*H + c - H];
}

// ---------------- mean aggregation (CSR gather) ----------------
__global__ __launch_bounds__(256) void k_agg(const float* __restrict__ h,
                                             float* __restrict__ agg) {
    int n = blockIdx.x;
    int f = threadIdx.x;
    int s = g_off[n], e = g_off[n+1];
    __shared__ int nb[256];
    float acc = 0.f;
    for (int base = s; base < e; base += 256) {
        int m = min(256, e - base);
        if (f < m) nb[f] = g_csrs[base + f];
        __syncthreads();
        for (int j = 0; j < m; j++)
            acc += h[(size_t)nb[j]*H + f];
        __syncthreads();
    }
    agg[(size_t)n*H + f] = acc / g_degf[n];
}

// ---------------- generic SGEMM: C[M,Ncols] (=|+=) A[M,K] * B[Ncols,K]^T + bias ----------------
#define BM 128
#define BN 64
#define BK 16

__global__ __launch_bounds__(256) void k_sgemm(
    const float* __restrict__ A, int lda,
    const float* __restrict__ B, int ldb,
    float* __restrict__ C, int ldc,
    int M, int K,
    const float* __restrict__ bias,
    int accum, int ashift)
{
    __shared__ float As[BK][BM];
    __shared__ float Bs[BK][BN];
    int bm = blockIdx.y * BM;
    int bn = blockIdx.x * BN;
    int t  = threadIdx.x;
    int tx = t & 15, ty = t >> 4;

    float acc[8][4];
    #pragma unroll
    for (int i = 0; i < 8; i++)
        #pragma unroll
        for (int j = 0; j < 4; j++) acc[i][j] = 0.f;

    for (int k0 = 0; k0 < K; k0 += BK) {
        #pragma unroll
        for (int l = 0; l < 8; l++) {
            int flat = t + l*256;
            int ar = flat >> 4, ak = flat & 15;
            int gr = bm + ar + ashift;
            As[ak][ar] = (gr >= 0 && gr < M) ? A[(size_t)gr*lda + k0 + ak] : 0.f;
        }
        #pragma unroll
        for (int l = 0; l < 4; l++) {
            int flat = t + l*256;
            int br = flat >> 4, bk = flat & 15;
            Bs[bk][br] = B[(size_t)(bn + br)*ldb + k0 + bk];
        }
        __syncthreads();
        #pragma unroll
        for (int kk = 0; kk < BK; kk++) {
            float4 a0 = *(const float4*)&As[kk][ty*8];
            float4 a1 = *(const float4*)&As[kk][ty*8 + 4];
            float4 b0 = *(const float4*)&Bs[kk][tx*4];
            float aa[8] = {a0.x,a0.y,a0.z,a0.w,a1.x,a1.y,a1.z,a1.w};
            float bb[4] = {b0.x,b0.y,b0.z,b0.w};
            #pragma unroll
            for (int i = 0; i < 8; i++)
                #pragma unroll
                for (int j = 0; j < 4; j++)
                    acc[i][j] += aa[i]*bb[j];
        }
        __syncthreads();
    }
    #pragma unroll
    for (int i = 0; i < 8; i++) {
        int row = bm + ty*8 + i;
        #pragma unroll
        for (int j = 0; j < 4; j++) {
            int col = bn + tx*4 + j;
            float v = acc[i][j];
            if (bias) v += bias[col];
            size_t idx = (size_t)row*ldc + col;
            if (accum) C[idx] += v;
            else       C[idx] = v;
        }
    }
}

// ---------------- LayerNorm / activation epilogue ----------------
#define F_LN       1
#define F_POSTRELU 2
#define F_RES      4
#define F_PRERELU  8

__global__ __launch_bounds__(256) void k_ln(
    const float* __restrict__ x, const float* __restrict__ g, const float* __restrict__ b,
    const float* __restrict__ res, float* __restrict__ out, int W, int flags)
{
    __shared__ float rs[8], rq[8];
    __shared__ float s_mean, s_rstd;
    int row = blockIdx.x, t = threadIdx.x;
    const float* xr = x + (size_t)row*W;
    int two = (W == 512);
    float v0 = xr[t];
    float v1 = two ? xr[t + 256] : 0.f;
    if (flags & F_PRERELU) { v0 = fmaxf(v0, 0.f); v1 = fmaxf(v1, 0.f); }
    float s = v0 + v1, sq = v0*v0 + v1*v1;
    #pragma unroll
    for (int o = 16; o > 0; o >>= 1) {
        s  += __shfl_xor_sync(0xffffffff, s,  o);
        sq += __shfl_xor_sync(0xffffffff, sq, o);
    }
    int warp = t >> 5, lane = t & 31;
    if (lane == 0) { rs[warp] = s; rq[warp] = sq; }
    __syncthreads();
    if (t == 0) {
        float S = 0.f, Q = 0.f;
        #pragma unroll
        for (int w = 0; w < 8; w++) { S += rs[w]; Q += rq[w]; }
        float mean = S / (float)W;
        float var = fmaxf(Q / (float)W - mean*mean, 0.f);
        s_mean = mean;
        s_rstd = rsqrtf(var + 1e-5f);
    }
    __syncthreads();
    float mean = s_mean, rstd = s_rstd;

    float val = v0;
    if (flags & F_LN)       val = (val - mean)*rstd*g[t] + b[t];
    if (flags & F_POSTRELU) val = fmaxf(val, 0.f);
    if (flags & F_RES)      val += res[(size_t)row*W + t];
    out[(size_t)row*W + t] = val;

    if (two) {
        int c = t + 256;
        float val2 = v1;
        if (flags & F_LN)       val2 = (val2 - mean)*rstd*g[c] + b[c];
        if (flags & F_POSTRELU) val2 = fmaxf(val2, 0.f);
        if (flags & F_RES)      val2 += res[(size_t)row*W + c];
        out[(size_t)row*W + c] = val2;
    }
}

// ---------------- flash attention: 4 heads, hd=128, N=4096 ----------------
#define QP 132   // padded row stride (floats) for Q/KV tiles
#define SP 33    // padded row stride for S tile

__device__ __forceinline__ float dot4(float4 a, float4 b) {
    return a.x*b.x + a.y*b.y + a.z*b.z + a.w*b.w;
}

__global__ __launch_bounds__(128) void k_flash(const float* __restrict__ qkv,
                                               float* __restrict__ outp)
{
    __shared__ float Qs[32][QP];
    __shared__ float KVs[32][QP];
    __shared__ float Ss[32][SP];
    __shared__ float rowm[32], rowl[32], rowf[32];

    int qb = blockIdx.x;          // 0..127
    int head = blockIdx.y;        // 0..3
    int t = threadIdx.x;
    int n0 = qb*32;
    int coff = head*128;

    // load Q tile [32 x 128]
    #pragma unroll
    for (int l = 0; l < 8; l++) {
        int f4 = t + l*128;             // float4 index, 0..1023
        int r = f4 >> 5, c4 = f4 & 31;
        *(float4*)&Qs[r][c4*4] =
            *(const float4*)&qkv[(size_t)(n0 + r)*1536 + coff + c4*4];
    }
    if (t < 32) { rowm[t] = -1e30f; rowl[t] = 0.f; }

    float acc[4][8];
    #pragma unroll
    for (int i = 0; i < 4; i++)
        #pragma unroll
        for (int j = 0; j < 8; j++) acc[i][j] = 0.f;

    const float scale = 0.08838834764831845f;  // 1/sqrt(128)
    int sq = (t >> 3)*2, sk = (t & 7)*4;       // S: 2q x 4k per thread
    int q0 = (t >> 4)*4, d0 = (t & 15)*8;     // PV: 4q x 8d per thread

    for (int kb = 0; kb < 128; kb++) {
        __syncthreads();   // protect KVs (prev PV) and Qs (first iter)
        // load K tile
        #pragma unroll
        for (int l = 0; l < 8; l++) {
            int f4 = t + l*128;
            int r = f4 >> 5, c4 = f4 & 31;
            *(float4*)&KVs[r][c4*4] =
                *(const float4*)&qkv[(size_t)(kb*32 + r)*1536 + 512 + coff + c4*4];
        }
        __syncthreads();
        // S = Q K^T * scale
        float s00[2][4];
        #pragma unroll
        for (int i = 0; i < 2; i++)
            #pragma unroll
            for (int j = 0; j < 4; j++) s00[i][j] = 0.f;
        #pragma unroll 8
        for (int d = 0; d < 128; d += 4) {
            float4 a0 = *(const float4*)&Qs[sq  ][d];
            float4 a1 = *(const float4*)&Qs[sq+1][d];
            float4 b0 = *(const float4*)&KVs[sk  ][d];
            float4 b1 = *(const float4*)&KVs[sk+1][d];
            float4 b2 = *(const float4*)&KVs[sk+2][d];
            float4 b3 = *(const float4*)&KVs[sk+3][d];
            s00[0][0] += dot4(a0,b0); s00[0][1] += dot4(a0,b1);
            s00[0][2] += dot4(a0,b2); s00[0][3] += dot4(a0,b3);
            s00[1][0] += dot4(a1,b0); s00[1][1] += dot4(a1,b1);
            s00[1][2] += dot4(a1,b2); s00[1][3] += dot4(a1,b3);
        }
        #pragma unroll
        for (int i = 0; i < 2; i++)
            #pragma unroll
            for (int j = 0; j < 4; j++)
                Ss[sq+i][sk+j] = s00[i][j]*scale;
        __syncthreads();
        // load V tile (overwrites K — consumed) concurrently with softmax
        #pragma unroll
        for (int l = 0; l < 8; l++) {
            int f4 = t + l*128;
            int r = f4 >> 5, c4 = f4 & 31;
            *(float4*)&KVs[r][c4*4] =
                *(const float4*)&qkv[(size_t)(kb*32 + r)*1536 + 1024 + coff + c4*4];
        }
        if (t < 32) {
            int q = t;
            float mold = rowm[q];
            float mx = mold;
            #pragma unroll
            for (int kk = 0; kk < 32; kk++) mx = fmaxf(mx, Ss[q][kk]);
            float f = __expf(mold - mx);
            float lsum = 0.f;
            #pragma unroll
            for (int kk = 0; kk < 32; kk++) {
                float p = __expf(Ss[q][kk] - mx);
                Ss[q][kk] = p;
                lsum += p;
            }
            rowl[q] = rowl[q]*f + lsum;
            rowm[q] = mx;
            rowf[q] = f;
        }
        __syncthreads();
        // O = O*f + P V
        #pragma unroll
        for (int i = 0; i < 4; i++) {
            float f = rowf[q0 + i];
            #pragma unroll
            for (int j = 0; j < 8; j++) acc[i][j] *= f;
        }
        #pragma unroll 4
        for (int kk = 0; kk < 32; kk++) {
            float p[4];
            #pragma unroll
            for (int i = 0; i < 4; i++) p[i] = Ss[q0+i][kk];
            float4 v0 = *(const float4*)&KVs[kk][d0];
            float4 v1 = *(const float4*)&KVs[kk][d0+4];
            #pragma unroll
            for (int i = 0; i < 4; i++) {
                acc[i][0] += p[i]*v0.x; acc[i][1] += p[i]*v0.y;
                acc[i][2] += p[i]*v0.z; acc[i][3] += p[i]*v0.w;
                acc[i][4] += p[i]*v1.x; acc[i][5] += p[i]*v1.y;
                acc[i][6] += p[i]*v1.z; acc[i][7] += p[i]*v1.w;
            }
        }
    }
    __syncthreads();
    #pragma unroll
    for (int i = 0; i < 4; i++) {
        float inv = 1.f / rowl[q0 + i];
        int row = n0 + q0 + i;
        #pragma unroll
        for (int j = 0; j < 8; j++)
            outp[(size_t)row*512 + coff + d0 + j] = acc[i][j]*inv;
    }
}

// ---------------- launch ----------------
extern "C" void kernel_launch(void* const* d_in, const int* in_sizes, int n_in,
                              void* d_out, int out_size) {
    const float* x          = (const float*)d_in[0];
    const int*   ei         = (const int*)  d_in[1];
    const float* sage_wl    = (const float*)d_in[2];
    const float* sage_wr    = (const float*)d_in[3];
    const float* sage_bl    = (const float*)d_in[4];
    const float* ln_g       = (const float*)d_in[5];
    const float* ln_b       = (const float*)d_in[6];
    const float* conv_w     = (const float*)d_in[7];
    const float* conv_b     = (const float*)d_in[8];
    const float* cnorm_g    = (const float*)d_in[9];
    const float* cnorm_b    = (const float*)d_in[10];
    const float* in_proj_w  = (const float*)d_in[11];
    const float* in_proj_b  = (const float*)d_in[12];
    const float* out_proj_w = (const float*)d_in[13];
    const float* out_proj_b = (const float*)d_in[14];
    const float* anorm_g    = (const float*)d_in[15];
    const float* anorm_b    = (const float*)d_in[16];
    const float* fuse_w     = (const float*)d_in[17];
    const float* fuse_b     = (const float*)d_in[18];
    float* outp = (float*)d_out;

    float *ph, *pagg, *ptmp, *pca, *pcb, *pfused, *pqkv, *pattn, *po, *po2, *pconvw;
    cudaGetSymbolAddress((void**)&ph,     g_h);
    cudaGetSymbolAddress((void**)&pagg,   g_agg);
    cudaGetSymbolAddress((void**)&ptmp,   g_tmp);
    cudaGetSymbolAddress((void**)&pca,    g_ca);
    cudaGetSymbolAddress((void**)&pcb,    g_cb);
    cudaGetSymbolAddress((void**)&pfused, g_fused);
    cudaGetSymbolAddress((void**)&pqkv,   g_qkv);
    cudaGetSymbolAddress((void**)&pattn,  g_attn);
    cudaGetSymbolAddress((void**)&po,     g_o);
    cudaGetSymbolAddress((void**)&po2,    g_o2);
    cudaGetSymbolAddress((void**)&pconvw, g_convw);

    // CSR build
    k_zero<<<16, 256>>>();
    k_count<<<E_EDGES/256, 256>>>(ei + E_EDGES);     // dst row
    k_scan<<<1, 1024>>>();
    k_fill<<<E_EDGES/256, 256>>>(ei, ei + E_EDGES);  // src, dst
    k_wtrans<<<(9*H*H + 255)/256, 256>>>(conv_w, pconvw);
    k_copy<<<N_NODES*H/256, 256>>>(x, ph);

    dim3 g_hh(H/BN, N_NODES/BM);       // (4, 32) for 4096x256 GEMMs

    // ---- GNN: 6 SAGE layers ----
    for (int i = 0; i < 6; i++) {
        k_agg<<<N_NODES, 256>>>(ph, pagg);
        k_sgemm<<<g_hh, 256>>>(pagg, H, sage_wl + i*H*H, H, ptmp, H,
                               N_NODES, H, sage_bl + i*H, 0, 0);
        k_sgemm<<<g_hh, 256>>>(ph,   H, sage_wr + i*H*H, H, ptmp, H,
                               N_NODES, H, nullptr, 1, 0);
        int flags = (i < 5) ? (F_LN | F_POSTRELU | F_RES) : (F_POSTRELU | F_RES);
        k_ln<<<N_NODES, 256>>>(ptmp, (i < 5) ? ln_g + i*H : nullptr,
                               (i < 5) ? ln_b + i*H : nullptr,
                               ph, ph, H, flags);
    }

    // ---- CNN branch (3 conv1d K=3, pad 1, over node axis) ----
    const float* cin = ph;
    float* couts[2] = {pca, pcb};
    for (int j = 0; j < 3; j++) {
        for (int k = 0; k < 3; k++) {
            k_sgemm<<<g_hh, 256>>>(cin, H, pconvw + (size_t)(j*3 + k)*H*H, H,
                                   ptmp, H, N_NODES, H,
                                   (k == 0) ? conv_b + j*H : nullptr,
                                   (k != 0), k - 1);
        }
        float* co = couts[j & 1];
        k_ln<<<N_NODES, 256>>>(ptmp, cnorm_g + j*H, cnorm_b + j*H,
                               nullptr, co, H, F_LN | F_PRERELU);
        cin = co;
    }

    // ---- concat + attention ----
    k_concat<<<N_NODES*512/256, 256>>>(ph, cin, pfused);
    dim3 g_qkvd(1536/BN, N_NODES/BM);
    k_sgemm<<<g_qkvd, 256>>>(pfused, 512, in_proj_w, 512, pqkv, 1536,
                             N_NODES, 512, in_proj_b, 0, 0);
    dim3 g_fl(128, 4);
    k_flash<<<g_fl, 128>>>(pqkv, pattn);
    dim3 g_op(512/BN, N_NODES/BM);
    k_sgemm<<<g_op, 256>>>(pattn, 512, out_proj_w, 512, po, 512,
                           N_NODES, 512, out_proj_b, 0, 0);
    k_ln<<<N_NODES, 256>>>(po, anorm_g, anorm_b, nullptr, po2, 512, F_LN);
    dim3 g_fu(64/BN, N_NODES/BM);
    k_sgemm<<<g_fu, 256>>>(po2, 512, fuse_w, 512, outp, 64,
                           N_NODES, 512, fuse_b, 0, 0);
}

// round 3
// speedup vs baseline: 1.4013x; 1.4013x over previous
#include <cuda_runtime.h>
#include <math.h>

#define N_NODES 4096
#define H 256
#define E_EDGES 131072

// ---------------- scratch (device globals: no allocs allowed) ----------------
__device__ float g_h[N_NODES*H];
__device__ float g_agg[N_NODES*H];
__device__ float g_tmp[N_NODES*H];
__device__ float g_ca[N_NODES*H];
__device__ float g_cb[N_NODES*H];
__device__ float g_qkv[N_NODES*6*H];
__device__ float g_attn[N_NODES*2*H];
__device__ float g_o[N_NODES*2*H];
__device__ float g_o2[N_NODES*2*H];
__device__ float g_sagew[6*H*2*H];     // [6][256][512]  = [wl | wr]
__device__ float g_convw[3*H*3*H];     // [3][256][768]  = taps k=0,1,2
__device__ int   g_cnt[N_NODES];
__device__ int   g_fillp[N_NODES];
__device__ int   g_off[N_NODES+1];
__device__ int   g_csrs[E_EDGES];
__device__ float g_degf[N_NODES];

// ---------------- CSR build ----------------
__global__ void k_zero() {
    int i = blockIdx.x*256 + threadIdx.x;
    if (i < N_NODES) { g_cnt[i] = 0; g_fillp[i] = 0; }
}

__global__ void k_count(const int* __restrict__ dst) {
    int e = blockIdx.x*256 + threadIdx.x;
    if (e < E_EDGES) atomicAdd(&g_cnt[dst[e]], 1);
}

__global__ void k_scan() {
    __shared__ int ps[1024];
    int t = threadIdx.x;
    int c[4]; int s = 0;
    #pragma unroll
    for (int l = 0; l < 4; l++) { c[l] = g_cnt[t*4+l]; s += c[l]; }
    ps[t] = s;
    __syncthreads();
    for (int d = 1; d < 1024; d <<= 1) {
        int v = (t >= d) ? ps[t-d] : 0;
        __syncthreads();
        ps[t] += v;
        __syncthreads();
    }
    int base = ps[t] - s;
    #pragma unroll
    for (int l = 0; l < 4; l++) {
        g_off[t*4+l] = base;
        base += c[l];
        g_degf[t*4+l] = (float)max(c[l], 1);
    }
    if (t == 1023) g_off[N_NODES] = ps[1023];
}

__global__ void k_fill(const int* __restrict__ src, const int* __restrict__ dst) {
    int e = blockIdx.x*256 + threadIdx.x;
    if (e < E_EDGES) {
        int d = dst[e];
        int p = atomicAdd(&g_fillp[d], 1);
        g_csrs[g_off[d] + p] = src[e];
    }
}

// ---------------- weight packing ----------------
// sage: out[l][o][c] = c<256 ? wl[l][o][c] : wr[l][o][c-256]
__global__ void k_packsage(const float* __restrict__ wl, const float* __restrict__ wr,
                           float* __restrict__ out) {
    int idx = blockIdx.x*256 + threadIdx.x;     // 6*256*512
    if (idx < 6*H*2*H) {
        int c = idx & 511;
        int r = idx >> 9;                       // l*256 + o
        out[idx] = (c < H) ? wl[r*H + c] : wr[r*H + (c - H)];
    }
}

// conv_w [3][O][I][K=3] -> out[j][o][k*256+i]
__global__ void k_packconv(const float* __restrict__ w, float* __restrict__ out) {
    int idx = blockIdx.x*256 + threadIdx.x;     // 3*256*768
    if (idx < 3*H*3*H) {
        int c = idx % 768;
        int r = idx / 768;                      // j*256 + o
        int k = c >> 8;
        int i = c & 255;
        out[idx] = w[(size_t)(r*H + i)*3 + k];
    }
}

// ---------------- mean aggregation (CSR gather) ----------------
__global__ __launch_bounds__(256) void k_agg(const float* __restrict__ h,
                                             float* __restrict__ agg) {
    int n = blockIdx.x;
    int f = threadIdx.x;
    int s = g_off[n], e = g_off[n+1];
    __shared__ int nb[256];
    float acc = 0.f;
    for (int base = s; base < e; base += 256) {
        int m = min(256, e - base);
        if (f < m) nb[f] = g_csrs[base + f];
        __syncthreads();
        for (int j = 0; j < m; j++)
            acc += h[(size_t)nb[j]*H + f];
        __syncthreads();
    }
    agg[(size_t)n*H + f] = acc / g_degf[n];
}

// ---------------- segmented SGEMM ----------------
// C[M,Ncols] = [A0 A1 A2] * B^T + bias
// K split into 256-wide segments; segment s has base pointer As, row-stride lds,
// row shift shs (rows outside [0,M) read as 0).
#define BM 128
#define BN 64
#define BK 16

__global__ __launch_bounds__(256) void k_sgemm(
    const float* __restrict__ A0, int ld0, int sh0,
    const float* __restrict__ A1, int ld1, int sh1,
    const float* __restrict__ A2, int ld2, int sh2,
    const float* __restrict__ B, int ldb,
    float* __restrict__ C, int ldc,
    int M, int K,
    const float* __restrict__ bias)
{
    __shared__ float As[BK][BM];
    __shared__ float Bs[BK][BN];
    int bm = blockIdx.y * BM;
    int bn = blockIdx.x * BN;
    int t  = threadIdx.x;
    int tx = t & 15, ty = t >> 4;

    float acc[8][4];
    #pragma unroll
    for (int i = 0; i < 8; i++)
        #pragma unroll
        for (int j = 0; j < 4; j++) acc[i][j] = 0.f;

    for (int k0 = 0; k0 < K; k0 += BK) {
        int seg = k0 >> 8;
        const float* A = (seg == 0) ? A0 : (seg == 1) ? A1 : A2;
        int lda = (seg == 0) ? ld0 : (seg == 1) ? ld1 : ld2;
        int sh  = (seg == 0) ? sh0 : (seg == 1) ? sh1 : sh2;
        int kc  = k0 & 255;
        #pragma unroll
        for (int l = 0; l < 8; l++) {
            int flat = t + l*256;
            int ar = flat >> 4, ak = flat & 15;
            int gr = bm + ar + sh;
            As[ak][ar] = (gr >= 0 && gr < M) ? A[(size_t)gr*lda + kc + ak] : 0.f;
        }
        #pragma unroll
        for (int l = 0; l < 4; l++) {
            int flat = t + l*256;
            int br = flat >> 4, bk = flat & 15;
            Bs[bk][br] = B[(size_t)(bn + br)*ldb + k0 + bk];
        }
        __syncthreads();
        #pragma unroll
        for (int kk = 0; kk < BK; kk++) {
            float4 a0 = *(const float4*)&As[kk][ty*8];
            float4 a1 = *(const float4*)&As[kk][ty*8 + 4];
            float4 b0 = *(const float4*)&Bs[kk][tx*4];
            float aa[8] = {a0.x,a0.y,a0.z,a0.w,a1.x,a1.y,a1.z,a1.w};
            float bb[4] = {b0.x,b0.y,b0.z,b0.w};
            #pragma unroll
            for (int i = 0; i < 8; i++)
                #pragma unroll
                for (int j = 0; j < 4; j++)
                    acc[i][j] += aa[i]*bb[j];
        }
        __syncthreads();
    }
    #pragma unroll
    for (int i = 0; i < 8; i++) {
        int row = bm + ty*8 + i;
        #pragma unroll
        for (int j = 0; j < 4; j++) {
            int col = bn + tx*4 + j;
            C[(size_t)row*ldc + col] = acc[i][j] + bias[col];
        }
    }
}

// ---------------- LayerNorm / activation epilogue ----------------
#define F_LN       1
#define F_POSTRELU 2
#define F_RES      4
#define F_PRERELU  8

__global__ __launch_bounds__(256) void k_ln(
    const float* __restrict__ x, const float* __restrict__ g, const float* __restrict__ b,
    const float* __restrict__ res, float* __restrict__ out, int W, int flags)
{
    __shared__ float rs[8], rq[8];
    __shared__ float s_mean, s_rstd;
    int row = blockIdx.x, t = threadIdx.x;
    const float* xr = x + (size_t)row*W;
    int two = (W == 512);
    float v0 = xr[t];
    float v1 = two ? xr[t + 256] : 0.f;
    if (flags & F_PRERELU) { v0 = fmaxf(v0, 0.f); v1 = fmaxf(v1, 0.f); }
    float s = v0 + v1, sq = v0*v0 + v1*v1;
    #pragma unroll
    for (int o = 16; o > 0; o >>= 1) {
        s  += __shfl_xor_sync(0xffffffff, s,  o);
        sq += __shfl_xor_sync(0xffffffff, sq, o);
    }
    int warp = t >> 5, lane = t & 31;
    if (lane == 0) { rs[warp] = s; rq[warp] = sq; }
    __syncthreads();
    if (t == 0) {
        float S = 0.f, Q = 0.f;
        #pragma unroll
        for (int w = 0; w < 8; w++) { S += rs[w]; Q += rq[w]; }
        float mean = S / (float)W;
        float var = fmaxf(Q / (float)W - mean*mean, 0.f);
        s_mean = mean;
        s_rstd = rsqrtf(var + 1e-5f);
    }
    __syncthreads();
    float mean = s_mean, rstd = s_rstd;

    float val = v0;
    if (flags & F_LN)       val = (val - mean)*rstd*g[t] + b[t];
    if (flags & F_POSTRELU) val = fmaxf(val, 0.f);
    if (flags & F_RES)      val += res[(size_t)row*W + t];
    out[(size_t)row*W + t] = val;

    if (two) {
        int c = t + 256;
        float val2 = v1;
        if (flags & F_LN)       val2 = (val2 - mean)*rstd*g[c] + b[c];
        if (flags & F_POSTRELU) val2 = fmaxf(val2, 0.f);
        if (flags & F_RES)      val2 += res[(size_t)row*W + c];
        out[(size_t)row*W + c] = val2;
    }
}

// ---------------- flash attention: 4 heads, hd=128, N=4096 ----------------
// BQ=64, BKV=64, 256 threads, dynamic smem
#define DP 132   // padded row stride (floats), 528B = 16B-aligned rows
#define SPD 68   // padded S row stride, 272B = 16B-aligned rows

__device__ __forceinline__ float dot4(float4 a, float4 b) {
    return a.x*b.x + a.y*b.y + a.z*b.z + a.w*b.w;
}

__global__ __launch_bounds__(256) void k_flash(const float* __restrict__ qkv,
                                               float* __restrict__ outp)
{
    extern __shared__ float sm[];
    float* Qs  = sm;                  // [64][132]
    float* KVs = sm + 64*DP;          // [64][132]
    float* Ss  = sm + 2*64*DP;        // [64][68]
    float* rowm = Ss + 64*SPD;        // [64]
    float* rowl = rowm + 64;
    float* rowf = rowl + 64;

    int qb = blockIdx.x;              // 0..63
    int head = blockIdx.y;            // 0..3
    int t = threadIdx.x;
    int n0 = qb*64;
    int coff = head*128;

    // load Q tile [64 x 128]
    #pragma unroll
    for (int l = 0; l < 8; l++) {
        int f4 = t + l*256;           // 0..2047
        int r = f4 >> 5, c4 = f4 & 31;
        *(float4*)&Qs[r*DP + c4*4] =
            *(const float4*)&qkv[(size_t)(n0 + r)*1536 + coff + c4*4];
    }
    if (t < 64) { rowm[t] = -1e30f; rowl[t] = 0.f; }

    float acc[4][8];
    #pragma unroll
    for (int i = 0; i < 4; i++)
        #pragma unroll
        for (int j = 0; j < 8; j++) acc[i][j] = 0.f;

    const float scale = 0.08838834764831845f;  // 1/sqrt(128)
    int sq = (t >> 4)*4, sk = (t & 15)*4;      // S: 4q x 4k per thread
    int pq = sq, pd = (t & 15)*8;              // PV: 4q x 8d per thread

    for (int kb = 0; kb < 64; kb++) {
        __syncthreads();   // KVs free (prev PV done), Qs ready (1st iter)
        // load K tile
        #pragma unroll
        for (int l = 0; l < 8; l++) {
            int f4 = t + l*256;
            int r = f4 >> 5, c4 = f4 & 31;
            *(float4*)&KVs[r*DP + c4*4] =
                *(const float4*)&qkv[(size_t)(kb*64 + r)*1536 + 512 + coff + c4*4];
        }
        __syncthreads();
        // S = Q K^T * scale (4x4 microtile)
        float s4[4][4];
        #pragma unroll
        for (int i = 0; i < 4; i++)
            #pragma unroll
            for (int j = 0; j < 4; j++) s4[i][j] = 0.f;
        #pragma unroll 8
        for (int d = 0; d < 128; d += 4) {
            float4 a0 = *(const float4*)&Qs[(sq+0)*DP + d];
            float4 a1 = *(const float4*)&Qs[(sq+1)*DP + d];
            float4 a2 = *(const float4*)&Qs[(sq+2)*DP + d];
            float4 a3 = *(const float4*)&Qs[(sq+3)*DP + d];
            float4 b0 = *(const float4*)&KVs[(sk+0)*DP + d];
            float4 b1 = *(const float4*)&KVs[(sk+1)*DP + d];
            float4 b2 = *(const float4*)&KVs[(sk+2)*DP + d];
            float4 b3 = *(const float4*)&KVs[(sk+3)*DP + d];
            s4[0][0] += dot4(a0,b0); s4[0][1] += dot4(a0,b1);
            s4[0][2] += dot4(a0,b2); s4[0][3] += dot4(a0,b3);
            s4[1][0] += dot4(a1,b0); s4[1][1] += dot4(a1,b1);
            s4[1][2] += dot4(a1,b2); s4[1][3] += dot4(a1,b3);
            s4[2][0] += dot4(a2,b0); s4[2][1] += dot4(a2,b1);
            s4[2][2] += dot4(a2,b2); s4[2][3] += dot4(a2,b3);
            s4[3][0] += dot4(a3,b0); s4[3][1] += dot4(a3,b1);
            s4[3][2] += dot4(a3,b2); s4[3][3] += dot4(a3,b3);
        }
        #pragma unroll
        for (int i = 0; i < 4; i++) {
            float4 v = make_float4(s4[i][0]*scale, s4[i][1]*scale,
                                   s4[i][2]*scale, s4[i][3]*scale);
            *(float4*)&Ss[(sq+i)*SPD + sk] = v;
        }
        __syncthreads();
        // load V tile (overwrites K — consumed); softmax runs concurrently
        #pragma unroll
        for (int l = 0; l < 8; l++) {
            int f4 = t + l*256;
            int r = f4 >> 5, c4 = f4 & 31;
            *(float4*)&KVs[r*DP + c4*4] =
                *(const float4*)&qkv[(size_t)(kb*64 + r)*1536 + 1024 + coff + c4*4];
        }
        if (t < 64) {
            int q = t;
            float mold = rowm[q];
            float mx = mold;
            #pragma unroll
            for (int kk = 0; kk < 64; kk++) mx = fmaxf(mx, Ss[q*SPD + kk]);
            float f = __expf(mold - mx);
            float lsum = 0.f;
            #pragma unroll
            for (int kk = 0; kk < 64; kk++) {
                float p = __expf(Ss[q*SPD + kk] - mx);
                Ss[q*SPD + kk] = p;
                lsum += p;
            }
            rowl[q] = rowl[q]*f + lsum;
            rowm[q] = mx;
            rowf[q] = f;
        }
        __syncthreads();
        // O = O*f + P V
        #pragma unroll
        for (int i = 0; i < 4; i++) {
            float f = rowf[pq + i];
            #pragma unroll
            for (int j = 0; j < 8; j++) acc[i][j] *= f;
        }
        #pragma unroll 4
        for (int kk = 0; kk < 64; kk++) {
            float p0 = Ss[(pq+0)*SPD + kk];
            float p1 = Ss[(pq+1)*SPD + kk];
            float p2 = Ss[(pq+2)*SPD + kk];
            float p3 = Ss[(pq+3)*SPD + kk];
            float4 v0 = *(const float4*)&KVs[kk*DP + pd];
            float4 v1 = *(const float4*)&KVs[kk*DP + pd + 4];
            acc[0][0] += p0*v0.x; acc[0][1] += p0*v0.y; acc[0][2] += p0*v0.z; acc[0][3] += p0*v0.w;
            acc[0][4] += p0*v1.x; acc[0][5] += p0*v1.y; acc[0][6] += p0*v1.z; acc[0][7] += p0*v1.w;
            acc[1][0] += p1*v0.x; acc[1][1] += p1*v0.y; acc[1][2] += p1*v0.z; acc[1][3] += p1*v0.w;
            acc[1][4] += p1*v1.x; acc[1][5] += p1*v1.y; acc[1][6] += p1*v1.z; acc[1][7] += p1*v1.w;
            acc[2][0] += p2*v0.x; acc[2][1] += p2*v0.y; acc[2][2] += p2*v0.z; acc[2][3] += p2*v0.w;
            acc[2][4] += p2*v1.x; acc[2][5] += p2*v1.y; acc[2][6] += p2*v1.z; acc[2][7] += p2*v1.w;
            acc[3][0] += p3*v0.x; acc[3][1] += p3*v0.y; acc[3][2] += p3*v0.z; acc[3][3] += p3*v0.w;
            acc[3][4] += p3*v1.x; acc[3][5] += p3*v1.y; acc[3][6] += p3*v1.z; acc[3][7] += p3*v1.w;
        }
    }
    #pragma unroll
    for (int i = 0; i < 4; i++) {
        float inv = 1.f / rowl[pq + i];
        int row = n0 + pq + i;
        #pragma unroll
        for (int j = 0; j < 8; j++)
            outp[(size_t)row*512 + coff + pd + j] = acc[i][j]*inv;
    }
}

// ---------------- launch ----------------
extern "C" void kernel_launch(void* const* d_in, const int* in_sizes, int n_in,
                              void* d_out, int out_size) {
    const float* x          = (const float*)d_in[0];
    const int*   ei         = (const int*)  d_in[1];
    const float* sage_wl    = (const float*)d_in[2];
    const float* sage_wr    = (const float*)d_in[3];
    const float* sage_bl    = (const float*)d_in[4];
    const float* ln_g       = (const float*)d_in[5];
    const float* ln_b       = (const float*)d_in[6];
    const float* conv_w     = (const float*)d_in[7];
    const float* conv_b     = (const float*)d_in[8];
    const float* cnorm_g    = (const float*)d_in[9];
    const float* cnorm_b    = (const float*)d_in[10];
    const float* in_proj_w  = (const float*)d_in[11];
    const float* in_proj_b  = (const float*)d_in[12];
    const float* out_proj_w = (const float*)d_in[13];
    const float* out_proj_b = (const float*)d_in[14];
    const float* anorm_g    = (const float*)d_in[15];
    const float* anorm_b    = (const float*)d_in[16];
    const float* fuse_w     = (const float*)d_in[17];
    const float* fuse_b     = (const float*)d_in[18];
    float* outp = (float*)d_out;

    float *ph, *pagg, *ptmp, *pca, *pcb, *pqkv, *pattn, *po, *po2, *psagew, *pconvw;
    cudaGetSymbolAddress((void**)&ph,     g_h);
    cudaGetSymbolAddress((void**)&pagg,   g_agg);
    cudaGetSymbolAddress((void**)&ptmp,   g_tmp);
    cudaGetSymbolAddress((void**)&pca,    g_ca);
    cudaGetSymbolAddress((void**)&pcb,    g_cb);
    cudaGetSymbolAddress((void**)&pqkv,   g_qkv);
    cudaGetSymbolAddress((void**)&pattn,  g_attn);
    cudaGetSymbolAddress((void**)&po,     g_o);
    cudaGetSymbolAddress((void**)&po2,    g_o2);
    cudaGetSymbolAddress((void**)&psagew, g_sagew);
    cudaGetSymbolAddress((void**)&pconvw, g_convw);

    // CSR build + weight packing
    k_zero<<<16, 256>>>();
    k_count<<<E_EDGES/256, 256>>>(ei + E_EDGES);
    k_scan<<<1, 1024>>>();
    k_fill<<<E_EDGES/256, 256>>>(ei, ei + E_EDGES);
    k_packsage<<<(6*H*2*H + 255)/256, 256>>>(sage_wl, sage_wr, psagew);
    k_packconv<<<(3*H*3*H + 255)/256, 256>>>(conv_w, pconvw);

    dim3 g_hh(H/BN, N_NODES/BM);   // (4, 32)

    // ---- GNN: 6 SAGE layers ----
    const float* hcur = x;
    for (int i = 0; i < 6; i++) {
        k_agg<<<N_NODES, 256>>>(hcur, pagg);
        // [agg | h] @ [wl ; wr]^T + bl   (K = 512, single GEMM)
        k_sgemm<<<g_hh, 256>>>(pagg, H, 0, hcur, H, 0, pagg, H, 0,
                               psagew + (size_t)i*H*2*H, 2*H,
                               ptmp, H, N_NODES, 2*H, sage_bl + i*H);
        int flags = (i < 5) ? (F_LN | F_POSTRELU | F_RES) : (F_POSTRELU | F_RES);
        k_ln<<<N_NODES, 256>>>(ptmp, (i < 5) ? ln_g + i*H : nullptr,
                               (i < 5) ? ln_b + i*H : nullptr,
                               hcur, ph, H, flags);
        hcur = ph;
    }

    // ---- CNN branch: 3 conv1d (K=3, pad 1) — one K=768 GEMM each ----
    const float* cin = ph;
    float* couts[3] = {pca, pcb, pca};
    for (int j = 0; j < 3; j++) {
        k_sgemm<<<g_hh, 256>>>(cin, H, -1, cin, H, 0, cin, H, 1,
                               pconvw + (size_t)j*H*3*H, 3*H,
                               ptmp, H, N_NODES, 3*H, conv_b + j*H);
        k_ln<<<N_NODES, 256>>>(ptmp, cnorm_g + j*H, cnorm_b + j*H,
                               nullptr, couts[j], H, F_LN | F_PRERELU);
        cin = couts[j];
    }

    // ---- qkv: [gnn | cnn] @ in_proj^T (virtual concat, K = 512) ----
    dim3 g_qkvd(1536/BN, N_NODES/BM);
    k_sgemm<<<g_qkvd, 256>>>(ph, H, 0, cin, H, 0, ph, H, 0,
                             in_proj_w, 512, pqkv, 1536,
                             N_NODES, 512, in_proj_b);

    // ---- flash attention ----
    size_t shm = (size_t)(2*64*DP + 64*SPD + 3*64) * sizeof(float);
    cudaFuncSetAttribute(k_flash, cudaFuncAttributeMaxDynamicSharedMemorySize, (int)shm);
    dim3 g_fl(64, 4);
    k_flash<<<g_fl, 256, shm>>>(pqkv, pattn);

    // ---- out_proj + LN + fuse ----
    dim3 g_op(512/BN, N_NODES/BM);
    k_sgemm<<<g_op, 256>>>(pattn, 512, 0, pattn + 256, 512, 0, pattn, 512, 0,
                           out_proj_w, 512, po, 512,
                           N_NODES, 512, out_proj_b);
    k_ln<<<N_NODES, 256>>>(po, anorm_g, anorm_b, nullptr, po2, 512, F_LN);
    dim3 g_fu(64/BN, N_NODES/BM);
    k_sgemm<<<g_fu, 256>>>(po2, 512, 0, po2 + 256, 512, 0, po2, 512, 0,
                           fuse_w, 512, outp, 64,
                           N_NODES, 512, fuse_b);
}

// round 4
// speedup vs baseline: 1.4024x; 1.0007x over previous
#include <cuda_runtime.h>
#include <math.h>

#define N_NODES 4096
#define H 256
#define E_EDGES 131072

// ---------------- scratch (device globals: no allocs allowed) ----------------
__device__ float g_h[N_NODES*H];
__device__ float g_agg[N_NODES*H];
__device__ float g_tmp[N_NODES*H];
__device__ float g_ca[N_NODES*H];
__device__ float g_cb[N_NODES*H];
__device__ float g_qkv[N_NODES*6*H];
__device__ float g_attn[N_NODES*2*H];
__device__ float g_o[N_NODES*2*H];
__device__ float g_o2[N_NODES*2*H];
__device__ float g_sagew[6*H*2*H];     // [6][256][512]  = [wl | wr]
__device__ float g_convw[3*H*3*H];     // [3][256][768]  = taps k=0,1,2
__device__ int   g_cnt[N_NODES];
__device__ int   g_fillp[N_NODES];
__device__ int   g_off[N_NODES+1];
__device__ int   g_csrs[E_EDGES];
__device__ float g_degf[N_NODES];

// ---------------- CSR build ----------------
__global__ void k_zero() {
    int i = blockIdx.x*256 + threadIdx.x;
    if (i < N_NODES) { g_cnt[i] = 0; g_fillp[i] = 0; }
}

__global__ void k_count(const int* __restrict__ dst) {
    int e = blockIdx.x*256 + threadIdx.x;
    if (e < E_EDGES) atomicAdd(&g_cnt[dst[e]], 1);
}

__global__ void k_scan() {
    __shared__ int ps[1024];
    int t = threadIdx.x;
    int c[4]; int s = 0;
    #pragma unroll
    for (int l = 0; l < 4; l++) { c[l] = g_cnt[t*4+l]; s += c[l]; }
    ps[t] = s;
    __syncthreads();
    for (int d = 1; d < 1024; d <<= 1) {
        int v = (t >= d) ? ps[t-d] : 0;
        __syncthreads();
        ps[t] += v;
        __syncthreads();
    }
    int base = ps[t] - s;
    #pragma unroll
    for (int l = 0; l < 4; l++) {
        g_off[t*4+l] = base;
        base += c[l];
        g_degf[t*4+l] = (float)max(c[l], 1);
    }
    if (t == 1023) g_off[N_NODES] = ps[1023];
}

__global__ void k_fill(const int* __restrict__ src, const int* __restrict__ dst) {
    int e = blockIdx.x*256 + threadIdx.x;
    if (e < E_EDGES) {
        int d = dst[e];
        int p = atomicAdd(&g_fillp[d], 1);
        g_csrs[g_off[d] + p] = src[e];
    }
}

// ---------------- weight packing ----------------
// sage: out[l][o][c] = c<256 ? wl[l][o][c] : wr[l][o][c-256]
__global__ void k_packsage(const float* __restrict__ wl, const float* __restrict__ wr,
                           float* __restrict__ out) {
    int idx = blockIdx.x*256 + threadIdx.x;     // 6*256*512
    if (idx < 6*H*2*H) {
        int c = idx & 511;
        int r = idx >> 9;                       // l*256 + o
        out[idx] = (c < H) ? wl[r*H + c] : wr[r*H + (c - H)];
    }
}

// conv_w [3][O][I][K=3] -> out[j][o][k*256+i]
__global__ void k_packconv(const float* __restrict__ w, float* __restrict__ out) {
    int idx = blockIdx.x*256 + threadIdx.x;     // 3*256*768
    if (idx < 3*H*3*H) {
        int c = idx % 768;
        int r = idx / 768;                      // j*256 + o
        int k = c >> 8;
        int i = c & 255;
        out[idx] = w[(size_t)(r*H + i)*3 + k];
    }
}

// ---------------- mean aggregation (CSR gather) ----------------
__global__ __launch_bounds__(256) void k_agg(const float* __restrict__ h,
                                             float* __restrict__ agg) {
    int n = blockIdx.x;
    int f = threadIdx.x;
    int s = g_off[n], e = g_off[n+1];
    __shared__ int nb[256];
    float acc = 0.f;
    for (int base = s; base < e; base += 256) {
        int m = min(256, e - base);
        if (f < m) nb[f] = g_csrs[base + f];
        __syncthreads();
        for (int j = 0; j < m; j++)
            acc += h[(size_t)nb[j]*H + f];
        __syncthreads();
    }
    agg[(size_t)n*H + f] = acc / g_degf[n];
}

// ---------------- segmented SGEMM ----------------
// C[M,Ncols] = [A0 A1 A2] * B^T + bias
// K split into 256-wide segments; segment s has base pointer As, row-stride lds,
// row shift shs (rows outside [0,M) read as 0).
#define BM 128
#define BN 64
#define BK 16

__global__ __launch_bounds__(256) void k_sgemm(
    const float* __restrict__ A0, int ld0, int sh0,
    const float* __restrict__ A1, int ld1, int sh1,
    const float* __restrict__ A2, int ld2, int sh2,
    const float* __restrict__ B, int ldb,
    float* __restrict__ C, int ldc,
    int M, int K,
    const float* __restrict__ bias)
{
    __shared__ float As[BK][BM];
    __shared__ float Bs[BK][BN];
    int bm = blockIdx.y * BM;
    int bn = blockIdx.x * BN;
    int t  = threadIdx.x;
    int tx = t & 15, ty = t >> 4;

    float acc[8][4];
    #pragma unroll
    for (int i = 0; i < 8; i++)
        #pragma unroll
        for (int j = 0; j < 4; j++) acc[i][j] = 0.f;

    for (int k0 = 0; k0 < K; k0 += BK) {
        int seg = k0 >> 8;
        const float* A = (seg == 0) ? A0 : (seg == 1) ? A1 : A2;
        int lda = (seg == 0) ? ld0 : (seg == 1) ? ld1 : ld2;
        int sh  = (seg == 0) ? sh0 : (seg == 1) ? sh1 : sh2;
        int kc  = k0 & 255;
        #pragma unroll
        for (int l = 0; l < 8; l++) {
            int flat = t + l*256;
            int ar = flat >> 4, ak = flat & 15;
            int gr = bm + ar + sh;
            As[ak][ar] = (gr >= 0 && gr < M) ? A[(size_t)gr*lda + kc + ak] : 0.f;
        }
        #pragma unroll
        for (int l = 0; l < 4; l++) {
            int flat = t + l*256;
            int br = flat >> 4, bk = flat & 15;
            Bs[bk][br] = B[(size_t)(bn + br)*ldb + k0 + bk];
        }
        __syncthreads();
        #pragma unroll
        for (int kk = 0; kk < BK; kk++) {
            float4 a0 = *(const float4*)&As[kk][ty*8];
            float4 a1 = *(const float4*)&As[kk][ty*8 + 4];
            float4 b0 = *(const float4*)&Bs[kk][tx*4];
            float aa[8] = {a0.x,a0.y,a0.z,a0.w,a1.x,a1.y,a1.z,a1.w};
            float bb[4] = {b0.x,b0.y,b0.z,b0.w};
            #pragma unroll
            for (int i = 0; i < 8; i++)
                #pragma unroll
                for (int j = 0; j < 4; j++)
                    acc[i][j] += aa[i]*bb[j];
        }
        __syncthreads();
    }
    #pragma unroll
    for (int i = 0; i < 8; i++) {
        int row = bm + ty*8 + i;
        #pragma unroll
        for (int j = 0; j < 4; j++) {
            int col = bn + tx*4 + j;
            C[(size_t)row*ldc + col] = acc[i][j] + bias[col];
        }
    }
}

// ---------------- LayerNorm / activation epilogue ----------------
#define F_LN       1
#define F_POSTRELU 2
#define F_RES      4
#define F_PRERELU  8

__global__ __launch_bounds__(256) void k_ln(
    const float* __restrict__ x, const float* __restrict__ g, const float* __restrict__ b,
    const float* __restrict__ res, float* __restrict__ out, int W, int flags)
{
    __shared__ float rs[8], rq[8];
    __shared__ float s_mean, s_rstd;
    int row = blockIdx.x, t = threadIdx.x;
    const float* xr = x + (size_t)row*W;
    int two = (W == 512);
    float v0 = xr[t];
    float v1 = two ? xr[t + 256] : 0.f;
    if (flags & F_PRERELU) { v0 = fmaxf(v0, 0.f); v1 = fmaxf(v1, 0.f); }
    float s = v0 + v1, sq = v0*v0 + v1*v1;
    #pragma unroll
    for (int o = 16; o > 0; o >>= 1) {
        s  += __shfl_xor_sync(0xffffffff, s,  o);
        sq += __shfl_xor_sync(0xffffffff, sq, o);
    }
    int warp = t >> 5, lane = t & 31;
    if (lane == 0) { rs[warp] = s; rq[warp] = sq; }
    __syncthreads();
    if (t == 0) {
        float S = 0.f, Q = 0.f;
        #pragma unroll
        for (int w = 0; w < 8; w++) { S += rs[w]; Q += rq[w]; }
        float mean = S / (float)W;
        float var = fmaxf(Q / (float)W - mean*mean, 0.f);
        s_mean = mean;
        s_rstd = rsqrtf(var + 1e-5f);
    }
    __syncthreads();
    float mean = s_mean, rstd = s_rstd;

    float val = v0;
    if (flags & F_LN)       val = (val - mean)*rstd*g[t] + b[t];
    if (flags & F_POSTRELU) val = fmaxf(val, 0.f);
    if (flags & F_RES)      val += res[(size_t)row*W + t];
    out[(size_t)row*W + t] = val;

    if (two) {
        int c = t + 256;
        float val2 = v1;
        if (flags & F_LN)       val2 = (val2 - mean)*rstd*g[c] + b[c];
        if (flags & F_POSTRELU) val2 = fmaxf(val2, 0.f);
        if (flags & F_RES)      val2 += res[(size_t)row*W + c];
        out[(size_t)row*W + c] = val2;
    }
}

// ---------------- flash attention: 4 heads, hd=128, N=4096 ----------------
// BQ=64, BKV=64, 256 threads, dynamic smem
#define DP 132   // padded row stride (floats), 528B = 16B-aligned rows
#define SPD 68   // padded S row stride, 272B = 16B-aligned rows

__device__ __forceinline__ float dot4(float4 a, float4 b) {
    return a.x*b.x + a.y*b.y + a.z*b.z + a.w*b.w;
}

__global__ __launch_bounds__(256) void k_flash(const float* __restrict__ qkv,
                                               float* __restrict__ outp)
{
    extern __shared__ float sm[];
    float* Qs  = sm;                  // [64][132]
    float* KVs = sm + 64*DP;          // [64][132]
    float* Ss  = sm + 2*64*DP;        // [64][68]
    float* rowm = Ss + 64*SPD;        // [64]
    float* rowl = rowm + 64;
    float* rowf = rowl + 64;

    int qb = blockIdx.x;              // 0..63
    int head = blockIdx.y;            // 0..3
    int t = threadIdx.x;
    int n0 = qb*64;
    int coff = head*128;

    // load Q tile [64 x 128]
    #pragma unroll
    for (int l = 0; l < 8; l++) {
        int f4 = t + l*256;           // 0..2047
        int r = f4 >> 5, c4 = f4 & 31;
        *(float4*)&Qs[r*DP + c4*4] =
            *(const float4*)&qkv[(size_t)(n0 + r)*1536 + coff + c4*4];
    }
    if (t < 64) { rowm[t] = -1e30f; rowl[t] = 0.f; }

    float acc[4][8];
    #pragma unroll
    for (int i = 0; i < 4; i++)
        #pragma unroll
        for (int j = 0; j < 8; j++) acc[i][j] = 0.f;

    const float scale = 0.08838834764831845f;  // 1/sqrt(128)
    int sq = (t >> 4)*4, sk = (t & 15)*4;      // S: 4q x 4k per thread
    int pq = sq, pd = (t & 15)*8;              // PV: 4q x 8d per thread

    for (int kb = 0; kb < 64; kb++) {
        __syncthreads();   // KVs free (prev PV done), Qs ready (1st iter)
        // load K tile
        #pragma unroll
        for (int l = 0; l < 8; l++) {
            int f4 = t + l*256;
            int r = f4 >> 5, c4 = f4 & 31;
            *(float4*)&KVs[r*DP + c4*4] =
                *(const float4*)&qkv[(size_t)(kb*64 + r)*1536 + 512 + coff + c4*4];
        }
        __syncthreads();
        // S = Q K^T * scale (4x4 microtile)
        float s4[4][4];
        #pragma unroll
        for (int i = 0; i < 4; i++)
            #pragma unroll
            for (int j = 0; j < 4; j++) s4[i][j] = 0.f;
        #pragma unroll 8
        for (int d = 0; d < 128; d += 4) {
            float4 a0 = *(const float4*)&Qs[(sq+0)*DP + d];
            float4 a1 = *(const float4*)&Qs[(sq+1)*DP + d];
            float4 a2 = *(const float4*)&Qs[(sq+2)*DP + d];
            float4 a3 = *(const float4*)&Qs[(sq+3)*DP + d];
            float4 b0 = *(const float4*)&KVs[(sk+0)*DP + d];
            float4 b1 = *(const float4*)&KVs[(sk+1)*DP + d];
            float4 b2 = *(const float4*)&KVs[(sk+2)*DP + d];
            float4 b3 = *(const float4*)&KVs[(sk+3)*DP + d];
            s4[0][0] += dot4(a0,b0); s4[0][1] += dot4(a0,b1);
            s4[0][2] += dot4(a0,b2); s4[0][3] += dot4(a0,b3);
            s4[1][0] += dot4(a1,b0); s4[1][1] += dot4(a1,b1);
            s4[1][2] += dot4(a1,b2); s4[1][3] += dot4(a1,b3);
            s4[2][0] += dot4(a2,b0); s4[2][1] += dot4(a2,b1);
            s4[2][2] += dot4(a2,b2); s4[2][3] += dot4(a2,b3);
            s4[3][0] += dot4(a3,b0); s4[3][1] += dot4(a3,b1);
            s4[3][2] += dot4(a3,b2); s4[3][3] += dot4(a3,b3);
        }
        #pragma unroll
        for (int i = 0; i < 4; i++) {
            float4 v = make_float4(s4[i][0]*scale, s4[i][1]*scale,
                                   s4[i][2]*scale, s4[i][3]*scale);
            *(float4*)&Ss[(sq+i)*SPD + sk] = v;
        }
        __syncthreads();
        // load V tile (overwrites K — consumed); softmax runs concurrently
        #pragma unroll
        for (int l = 0; l < 8; l++) {
            int f4 = t + l*256;
            int r = f4 >> 5, c4 = f4 & 31;
            *(float4*)&KVs[r*DP + c4*4] =
                *(const float4*)&qkv[(size_t)(kb*64 + r)*1536 + 1024 + coff + c4*4];
        }
        if (t < 64) {
            int q = t;
            float mold = rowm[q];
            float mx = mold;
            #pragma unroll
            for (int kk = 0; kk < 64; kk++) mx = fmaxf(mx, Ss[q*SPD + kk]);
            float f = __expf(mold - mx);
            float lsum = 0.f;
            #pragma unroll
            for (int kk = 0; kk < 64; kk++) {
                float p = __expf(Ss[q*SPD + kk] - mx);
                Ss[q*SPD + kk] = p;
                lsum += p;
            }
            rowl[q] = rowl[q]*f + lsum;
            rowm[q] = mx;
            rowf[q] = f;
        }
        __syncthreads();
        // O = O*f + P V
        #pragma unroll
        for (int i = 0; i < 4; i++) {
            float f = rowf[pq + i];
            #pragma unroll
            for (int j = 0; j < 8; j++) acc[i][j] *= f;
        }
        #pragma unroll 4
        for (int kk = 0; kk < 64; kk++) {
            float p0 = Ss[(pq+0)*SPD + kk];
            float p1 = Ss[(pq+1)*SPD + kk];
            float p2 = Ss[(pq+2)*SPD + kk];
            float p3 = Ss[(pq+3)*SPD + kk];
            float4 v0 = *(const float4*)&KVs[kk*DP + pd];
            float4 v1 = *(const float4*)&KVs[kk*DP + pd + 4];
            acc[0][0] += p0*v0.x; acc[0][1] += p0*v0.y; acc[0][2] += p0*v0.z; acc[0][3] += p0*v0.w;
            acc[0][4] += p0*v1.x; acc[0][5] += p0*v1.y; acc[0][6] += p0*v1.z; acc[0][7] += p0*v1.w;
            acc[1][0] += p1*v0.x; acc[1][1] += p1*v0.y; acc[1][2] += p1*v0.z; acc[1][3] += p1*v0.w;
            acc[1][4] += p1*v1.x; acc[1][5] += p1*v1.y; acc[1][6] += p1*v1.z; acc[1][7] += p1*v1.w;
            acc[2][0] += p2*v0.x; acc[2][1] += p2*v0.y; acc[2][2] += p2*v0.z; acc[2][3] += p2*v0.w;
            acc[2][4] += p2*v1.x; acc[2][5] += p2*v1.y; acc[2][6] += p2*v1.z; acc[2][7] += p2*v1.w;
            acc[3][0] += p3*v0.x; acc[3][1] += p3*v0.y; acc[3][2] += p3*v0.z; acc[3][3] += p3*v0.w;
            acc[3][4] += p3*v1.x; acc[3][5] += p3*v1.y; acc[3][6] += p3*v1.z; acc[3][7] += p3*v1.w;
        }
    }
    #pragma unroll
    for (int i = 0; i < 4; i++) {
        float inv = 1.f / rowl[pq + i];
        int row = n0 + pq + i;
        #pragma unroll
        for (int j = 0; j < 8; j++)
            outp[(size_t)row*512 + coff + pd + j] = acc[i][j]*inv;
    }
}

// ---------------- launch ----------------
extern "C" void kernel_launch(void* const* d_in, const int* in_sizes, int n_in,
                              void* d_out, int out_size) {
    const float* x          = (const float*)d_in[0];
    const int*   ei         = (const int*)  d_in[1];
    const float* sage_wl    = (const float*)d_in[2];
    const float* sage_wr    = (const float*)d_in[3];
    const float* sage_bl    = (const float*)d_in[4];
    const float* ln_g       = (const float*)d_in[5];
    const float* ln_b       = (const float*)d_in[6];
    const float* conv_w     = (const float*)d_in[7];
    const float* conv_b     = (const float*)d_in[8];
    const float* cnorm_g    = (const float*)d_in[9];
    const float* cnorm_b    = (const float*)d_in[10];
    const float* in_proj_w  = (const float*)d_in[11];
    const float* in_proj_b  = (const float*)d_in[12];
    const float* out_proj_w = (const float*)d_in[13];
    const float* out_proj_b = (const float*)d_in[14];
    const float* anorm_g    = (const float*)d_in[15];
    const float* anorm_b    = (const float*)d_in[16];
    const float* fuse_w     = (const float*)d_in[17];
    const float* fuse_b     = (const float*)d_in[18];
    float* outp = (float*)d_out;

    float *ph, *pagg, *ptmp, *pca, *pcb, *pqkv, *pattn, *po, *po2, *psagew, *pconvw;
    cudaGetSymbolAddress((void**)&ph,     g_h);
    cudaGetSymbolAddress((void**)&pagg,   g_agg);
    cudaGetSymbolAddress((void**)&ptmp,   g_tmp);
    cudaGetSymbolAddress((void**)&pca,    g_ca);
    cudaGetSymbolAddress((void**)&pcb,    g_cb);
    cudaGetSymbolAddress((void**)&pqkv,   g_qkv);
    cudaGetSymbolAddress((void**)&pattn,  g_attn);
    cudaGetSymbolAddress((void**)&po,     g_o);
    cudaGetSymbolAddress((void**)&po2,    g_o2);
    cudaGetSymbolAddress((void**)&psagew, g_sagew);
    cudaGetSymbolAddress((void**)&pconvw, g_convw);

    // CSR build + weight packing
    k_zero<<<16, 256>>>();
    k_count<<<E_EDGES/256, 256>>>(ei + E_EDGES);
    k_scan<<<1, 1024>>>();
    k_fill<<<E_EDGES/256, 256>>>(ei, ei + E_EDGES);
    k_packsage<<<(6*H*2*H + 255)/256, 256>>>(sage_wl, sage_wr, psagew);
    k_packconv<<<(3*H*3*H + 255)/256, 256>>>(conv_w, pconvw);

    dim3 g_hh(H/BN, N_NODES/BM);   // (4, 32)

    // ---- GNN: 6 SAGE layers ----
    const float* hcur = x;
    for (int i = 0; i < 6; i++) {
        k_agg<<<N_NODES, 256>>>(hcur, pagg);
        // [agg | h] @ [wl ; wr]^T + bl   (K = 512, single GEMM)
        k_sgemm<<<g_hh, 256>>>(pagg, H, 0, hcur, H, 0, pagg, H, 0,
                               psagew + (size_t)i*H*2*H, 2*H,
                               ptmp, H, N_NODES, 2*H, sage_bl + i*H);
        int flags = (i < 5) ? (F_LN | F_POSTRELU | F_RES) : (F_POSTRELU | F_RES);
        k_ln<<<N_NODES, 256>>>(ptmp, (i < 5) ? ln_g + i*H : nullptr,
                               (i < 5) ? ln_b + i*H : nullptr,
                               hcur, ph, H, flags);
        hcur = ph;
    }

    // ---- CNN branch: 3 conv1d (K=3, pad 1) — one K=768 GEMM each ----
    const float* cin = ph;
    float* couts[3] = {pca, pcb, pca};
    for (int j = 0; j < 3; j++) {
        k_sgemm<<<g_hh, 256>>>(cin, H, -1, cin, H, 0, cin, H, 1,
                               pconvw + (size_t)j*H*3*H, 3*H,
                               ptmp, H, N_NODES, 3*H, conv_b + j*H);
        k_ln<<<N_NODES, 256>>>(ptmp, cnorm_g + j*H, cnorm_b + j*H,
                               nullptr, couts[j], H, F_LN | F_PRERELU);
        cin = couts[j];
    }

    // ---- qkv: [gnn | cnn] @ in_proj^T (virtual concat, K = 512) ----
    dim3 g_qkvd(1536/BN, N_NODES/BM);
    k_sgemm<<<g_qkvd, 256>>>(ph, H, 0, cin, H, 0, ph, H, 0,
                             in_proj_w, 512, pqkv, 1536,
                             N_NODES, 512, in_proj_b);

    // ---- flash attention ----
    size_t shm = (size_t)(2*64*DP + 64*SPD + 3*64) * sizeof(float);
    cudaFuncSetAttribute(k_flash, cudaFuncAttributeMaxDynamicSharedMemorySize, (int)shm);
    dim3 g_fl(64, 4);
    k_flash<<<g_fl, 256, shm>>>(pqkv, pattn);

    // ---- out_proj + LN + fuse ----
    dim3 g_op(512/BN, N_NODES/BM);
    k_sgemm<<<g_op, 256>>>(pattn, 512, 0, pattn + 256, 512, 0, pattn, 512, 0,
                           out_proj_w, 512, po, 512,
                           N_NODES, 512, out_proj_b);
    k_ln<<<N_NODES, 256>>>(po, anorm_g, anorm_b, nullptr, po2, 512, F_LN);
    dim3 g_fu(64/BN, N_NODES/BM);
    k_sgemm<<<g_fu, 256>>>(po2, 512, 0, po2 + 256, 512, 0, po2, 512, 0,
                           fuse_w, 512, outp, 64,
                           N_NODES, 512, fuse_b);
}